// round 11
// baseline (speedup 1.0000x reference)
#include <cuda_runtime.h>
#include <cuda_bf16.h>

#define IMG_H 1080
#define IMG_W 1920
#define THR 20.0f

// Legacy run9 (border path only).
static __device__ __forceinline__ unsigned run9w(unsigned m16) {
    unsigned d = m16 * 0x10001u;
    unsigned r = d & __umulhi(d, 0x80000000u);
    r &= __umulhi(r, 0x40000000u);
    r &= __umulhi(r, 0x10000000u);
    r &= __umulhi(d, 0x01000000u);
    return r;
}

// Merged detection: 16 diffs -> 1.0f/0.0f.
// w = strong mask (|d|>=20), g = sign mask (d<0). A 9-window of all-strong
// same-sign samples at start i  <=>  W_i & B_{i+1..i+8}, where
// B = W & ~chg and chg_i = g_i ^ g_{i-1} (circular via 0x10001 duplication).
// One shift-AND cascade replaces two run9s. High bits self-clear (shifts
// bring zeros), so det != 0 <=> genuine detection; no final mask needed.
static __device__ __forceinline__ float detect16(const float* d) {
    unsigned g = 0u, ns = 0u;
#pragma unroll
    for (int i = 15; i >= 0; i--) {
        float s = __fmaf_rn(d[i], d[i], -400.0f);   // sign: |d|<20 (exact;
        g  = __funnelshift_l(__float_as_uint(d[i]), g, 1);  // |d|==20 -> +0 -> strong)
        ns = __funnelshift_l(__float_as_uint(s),    ns, 1);
    }
    unsigned w  = ~ns & 0xFFFFu;                    // strong bits
    unsigned W  = w * 0x10001u;                     // circular double copy
    unsigned G  = g * 0x10001u;
    unsigned chg = G ^ (G * 2u);                    // bit i = g_i ^ g_{i-1}
    unsigned B  = W & ~chg;                         // strong & same sign as prev
    unsigned b2 = B  & __umulhi(B,  0x80000000u);   // B & B>>1  : pairs
    unsigned b4 = b2 & __umulhi(b2, 0x40000000u);   // runs >= 4
    unsigned b8 = b4 & __umulhi(b4, 0x10000000u);   // runs >= 8
    unsigned det = W & __umulhi(b8, 0x80000000u);   // W_i & b8_{i+1}
    return __uint_as_float(min(det, 1u) * 0x3F800000u);
}

#define LOAD12(arr, q) { const float* _q=(q); \
    float4 _a=*(const float4*)(_q-4), _b=*(const float4*)(_q), _c=*(const float4*)(_q+4); \
    arr[0]=_a.x;arr[1]=_a.y;arr[2]=_a.z;arr[3]=_a.w; \
    arr[4]=_b.x;arr[5]=_b.y;arr[6]=_b.z;arr[7]=_b.w; \
    arr[8]=_c.x;arr[9]=_c.y;arr[10]=_c.z;arr[11]=_c.w; }
#define LOAD8(arr, q) { const float* _q=(q); \
    float2 _u=*(const float2*)(_q-2); float4 _v=*(const float4*)(_q); float2 _w=*(const float2*)(_q+4); \
    arr[0]=_u.x;arr[1]=_u.y;arr[2]=_v.x;arr[3]=_v.y;arr[4]=_v.z;arr[5]=_v.w;arr[6]=_w.x;arr[7]=_w.y; }
#define LOAD6(arr, q) { const float* _q=(q); \
    arr[0]=_q[-1]; float4 _v=*(const float4*)(_q); \
    arr[1]=_v.x;arr[2]=_v.y;arr[3]=_v.z;arr[4]=_v.w; arr[5]=_q[4]; }

__global__ __launch_bounds__(96)
void fast_score_kernel(const float* __restrict__ img, float* __restrict__ out, int N)
{
    const int DY[16] = { 0, 1, 2, 3, 3, 3, 2, 1, 0, -1, -2, -3, -3, -3, -2, -1};
    const int DX[16] = {-3, -3, -2, -1, 0, 1, 2, 3, 3, 3, 2, 1, 0, -1, -2, -3};

    int x0 = (blockIdx.x * 96 + threadIdx.x) * 4;
    int y0 = blockIdx.y * 4;            // centers y0 .. y0+3
    int n  = blockIdx.z;

    const float* im = img + (size_t)n * IMG_H * IMG_W;
    float* obase = out + ((size_t)n * IMG_H + y0) * IMG_W + x0;

    bool interior = (y0 >= 4) & (y0 <= IMG_H - 8) & (x0 >= 4) & (x0 <= IMG_W - 8);

    if (interior) {
        // Rolling rows (bases: 12w -> x0-4, 8w -> x0-2, 6w -> x0-1):
        // A:y0-3(6w) B:y0-2(8w) C:y0-1(12) D:y0(12) E:y0+1(12) F:y0+2(12)
        // G2:y0+3(12) H2:y0+4(12) I2:y0+5(8w) J2:y0+6(6w)
        float A[6], B[8], C[12], D[12], E[12], F[12], G2[12], H2[12], I2[8], J2[6];
        const float* row = im + (size_t)(y0 - 3) * IMG_W + x0;
        LOAD6 (A,  row); row += IMG_W;
        LOAD8 (B,  row); row += IMG_W;
        LOAD12(C,  row); row += IMG_W;
        LOAD12(D,  row); row += IMG_W;
        LOAD12(E,  row); row += IMG_W;
        LOAD12(F,  row); row += IMG_W;
        LOAD12(G2, row); row += IMG_W;

        float4 res;
        float* rp = (float*)&res;
        float dd[16];

        // ---- center y0 : R-3=A(6) R-2=B(8) R-1=C Rc=D R+1=E R+2=F R+3=G2(12)
#pragma unroll
        for (int p = 0; p < 4; p++) {
            float ctr = D[p + 4];
            dd[0]=D[p+1]-ctr;  dd[1]=E[p+1]-ctr;  dd[2]=F[p+2]-ctr;  dd[3]=G2[p+3]-ctr;
            dd[4]=G2[p+4]-ctr; dd[5]=G2[p+5]-ctr; dd[6]=F[p+6]-ctr;  dd[7]=E[p+7]-ctr;
            dd[8]=D[p+7]-ctr;  dd[9]=C[p+7]-ctr;  dd[10]=B[p+4]-ctr; dd[11]=A[p+2]-ctr;
            dd[12]=A[p+1]-ctr; dd[13]=A[p+0]-ctr; dd[14]=B[p+0]-ctr; dd[15]=C[p+1]-ctr;
            rp[p] = detect16(dd);
        }
        *(float4*)obase = res;

        LOAD12(H2, row); row += IMG_W;
        // ---- center y0+1 : R-3=B(8) R-2=C(12) R-1=D Rc=E R+1=F R+2=G2 R+3=H2(12)
#pragma unroll
        for (int p = 0; p < 4; p++) {
            float ctr = E[p + 4];
            dd[0]=E[p+1]-ctr;  dd[1]=F[p+1]-ctr;  dd[2]=G2[p+2]-ctr; dd[3]=H2[p+3]-ctr;
            dd[4]=H2[p+4]-ctr; dd[5]=H2[p+5]-ctr; dd[6]=G2[p+6]-ctr; dd[7]=F[p+7]-ctr;
            dd[8]=E[p+7]-ctr;  dd[9]=D[p+7]-ctr;  dd[10]=C[p+6]-ctr; dd[11]=B[p+3]-ctr;
            dd[12]=B[p+2]-ctr; dd[13]=B[p+1]-ctr; dd[14]=C[p+2]-ctr; dd[15]=D[p+1]-ctr;
            rp[p] = detect16(dd);
        }
        *(float4*)(obase + IMG_W) = res;

        LOAD8(I2, row); row += IMG_W;
        // ---- center y0+2 : R-3=C(12) R-2=D(12) R-1=E Rc=F R+1=G2 R+2=H2 R+3=I2(8)
#pragma unroll
        for (int p = 0; p < 4; p++) {
            float ctr = F[p + 4];
            dd[0]=F[p+1]-ctr;  dd[1]=G2[p+1]-ctr; dd[2]=H2[p+2]-ctr; dd[3]=I2[p+1]-ctr;
            dd[4]=I2[p+2]-ctr; dd[5]=I2[p+3]-ctr; dd[6]=H2[p+6]-ctr; dd[7]=G2[p+7]-ctr;
            dd[8]=F[p+7]-ctr;  dd[9]=E[p+7]-ctr;  dd[10]=D[p+6]-ctr; dd[11]=C[p+5]-ctr;
            dd[12]=C[p+4]-ctr; dd[13]=C[p+3]-ctr; dd[14]=D[p+2]-ctr; dd[15]=E[p+1]-ctr;
            rp[p] = detect16(dd);
        }
        *(float4*)(obase + 2 * IMG_W) = res;

        LOAD6(J2, row);
        // ---- center y0+3 : R-3=D(12) R-2=E(12) R-1=F Rc=G2 R+1=H2 R+2=I2(8) R+3=J2(6)
#pragma unroll
        for (int p = 0; p < 4; p++) {
            float ctr = G2[p + 4];
            dd[0]=G2[p+1]-ctr; dd[1]=H2[p+1]-ctr; dd[2]=I2[p+0]-ctr; dd[3]=J2[p+0]-ctr;
            dd[4]=J2[p+1]-ctr; dd[5]=J2[p+2]-ctr; dd[6]=I2[p+4]-ctr; dd[7]=H2[p+7]-ctr;
            dd[8]=G2[p+7]-ctr; dd[9]=F[p+7]-ctr;  dd[10]=E[p+6]-ctr; dd[11]=D[p+5]-ctr;
            dd[12]=D[p+4]-ctr; dd[13]=D[p+3]-ctr; dd[14]=E[p+2]-ctr; dd[15]=F[p+1]-ctr;
            rp[p] = detect16(dd);
        }
        *(float4*)(obase + 3 * IMG_W) = res;
    } else {
        // Border path: scalar loads with replicate-clamp (rare).
#pragma unroll
        for (int rr = 0; rr < 4; rr++) {
            int y = y0 + rr;
            float* op = obase + (size_t)rr * IMG_W;
#pragma unroll
            for (int p = 0; p < 4; p++) {
                int x = x0 + p;
                float center = __ldg(im + (size_t)y * IMG_W + x);
                unsigned dark = 0u, bright = 0u;
#pragma unroll
                for (int i = 0; i < 16; i++) {
                    int yy = min(max(y + DY[i], 0), IMG_H - 1);
                    int xx = min(max(x + DX[i], 0), IMG_W - 1);
                    float diff = __ldg(im + (size_t)yy * IMG_W + xx) - center;
                    if (diff >=  THR) dark   |= (1u << i);
                    if (diff <= -THR) bright |= (1u << i);
                }
                unsigned det = run9w(dark) | run9w(bright);
                op[p] = __uint_as_float(min(det, 1u) * 0x3F800000u);
            }
        }
    }
}

extern "C" void kernel_launch(void* const* d_in, const int* in_sizes, int n_in,
                              void* d_out, int out_size)
{
    const float* img = (const float*)d_in[0];
    float* out = (float*)d_out;
    int N = in_sizes[0] / (IMG_H * IMG_W);

    dim3 block(96, 1, 1);
    // x: 480 threads -> 5 blocks of 96;  y: 4 rows/thread -> 270
    dim3 grid(IMG_W / 4 / 96, IMG_H / 4, N);
    fast_score_kernel<<<grid, block>>>(img, out, N);
}

// round 12
// speedup vs baseline: 1.1903x; 1.1903x over previous
#include <cuda_runtime.h>
#include <cuda_bf16.h>

#define IMG_H 1080
#define IMG_W 1920
#define THR 20.0f

// Legacy run9 (border path only).
static __device__ __forceinline__ unsigned run9w(unsigned m16) {
    unsigned d = m16 * 0x10001u;
    unsigned r = d & __umulhi(d, 0x80000000u);
    r &= __umulhi(r, 0x40000000u);
    r &= __umulhi(r, 0x10000000u);
    r &= __umulhi(d, 0x01000000u);
    return r;
}

// Merged detection: 16 diffs -> 1.0f/0.0f. (Verified correct in R11.)
// w = strong mask (|d|>=20), g = sign mask (d<0). A 9-window of all-strong
// same-sign samples starting at i  <=>  W_i & B_{i+1..i+8}, where
// B = W & ~chg, chg_i = g_i ^ g_{i-1} (circular via the 0x10001 duplication).
// One shift-AND cascade replaces two run9s; high bits self-clear, det != 0
// iff genuine detection.
static __device__ __forceinline__ float detect16(const float* d) {
    unsigned g = 0u, ns = 0u;
#pragma unroll
    for (int i = 15; i >= 0; i--) {
        float s = __fmaf_rn(d[i], d[i], -400.0f);           // sign: |d|<20 (exact;
        g  = __funnelshift_l(__float_as_uint(d[i]), g, 1);  //  |d|==20 -> +0 -> strong)
        ns = __funnelshift_l(__float_as_uint(s),    ns, 1);
    }
    unsigned w  = ~ns & 0xFFFFu;                    // strong bits
    unsigned W  = w * 0x10001u;                     // circular double copy
    unsigned G  = g * 0x10001u;
    unsigned chg = G ^ (G * 2u);                    // bit i = g_i ^ g_{i-1}
    unsigned B  = W & ~chg;                         // strong & same sign as prev
    unsigned b2 = B  & __umulhi(B,  0x80000000u);   // runs >= 2
    unsigned b4 = b2 & __umulhi(b2, 0x40000000u);   // runs >= 4
    unsigned b8 = b4 & __umulhi(b4, 0x10000000u);   // runs >= 8
    unsigned det = W & __umulhi(b8, 0x80000000u);   // W_i & b8_{i+1}
    return __uint_as_float(min(det, 1u) * 0x3F800000u);
}

__global__ __launch_bounds__(96)
void fast_score_kernel(const float* __restrict__ img, float* __restrict__ out, int N)
{
    const int DY[16] = { 0, 1, 2, 3, 3, 3, 2, 1, 0, -1, -2, -3, -3, -3, -2, -1};
    const int DX[16] = {-3, -3, -2, -1, 0, 1, 2, 3, 3, 3, 2, 1, 0, -1, -2, -3};

    int x0 = (blockIdx.x * blockDim.x + threadIdx.x) * 4;
    int y0 = blockIdx.y * 2;            // this thread handles rows y0 and y0+1
    int n  = blockIdx.z;

    const float* im = img + (size_t)n * IMG_H * IMG_W;
    float* op0 = out + ((size_t)n * IMG_H + y0) * IMG_W + x0;
    float* op1 = op0 + IMG_W;

    bool interior = (y0 >= 4) & (y0 <= IMG_H - 6) & (x0 >= 4) & (x0 <= IMG_W - 8);

    if (interior) {
        // Union tile for both center rows (all loads front-batched):
        // T0: y0-3 [x0-1..x0+4](6)   T1: y0-2 [x0-2..x0+5](8)
        // T2: y0-1 [x0-4..x0+7](12)  T3: y0   [x0-4..x0+7](12)
        // T4: y0+1 [x0-4..x0+7](12)  T5: y0+2 [x0-4..x0+7](12)
        // T6: y0+3 [x0-2..x0+5](8)   T7: y0+4 [x0-1..x0+4](6)
        float T0[6], T1[8], T2[12], T3[12], T4[12], T5[12], T6[8], T7[6];
        {
            const float* p;
            p = im + (size_t)(y0 - 3) * IMG_W + x0;
            T0[0] = p[-1];
            { float4 v = *(const float4*)p; T0[1]=v.x; T0[2]=v.y; T0[3]=v.z; T0[4]=v.w; }
            T0[5] = p[4];
            p = im + (size_t)(y0 - 2) * IMG_W + x0;
            { float2 v = *(const float2*)(p - 2); T1[0]=v.x; T1[1]=v.y; }
            { float4 v = *(const float4*)p;       T1[2]=v.x; T1[3]=v.y; T1[4]=v.z; T1[5]=v.w; }
            { float2 v = *(const float2*)(p + 4); T1[6]=v.x; T1[7]=v.y; }
            p = im + (size_t)(y0 - 1) * IMG_W + (x0 - 4);
            { float4 a=*(const float4*)p, b=*(const float4*)(p+4), c=*(const float4*)(p+8);
              T2[0]=a.x;T2[1]=a.y;T2[2]=a.z;T2[3]=a.w;T2[4]=b.x;T2[5]=b.y;T2[6]=b.z;T2[7]=b.w;
              T2[8]=c.x;T2[9]=c.y;T2[10]=c.z;T2[11]=c.w; }
            p = im + (size_t)(y0) * IMG_W + (x0 - 4);
            { float4 a=*(const float4*)p, b=*(const float4*)(p+4), c=*(const float4*)(p+8);
              T3[0]=a.x;T3[1]=a.y;T3[2]=a.z;T3[3]=a.w;T3[4]=b.x;T3[5]=b.y;T3[6]=b.z;T3[7]=b.w;
              T3[8]=c.x;T3[9]=c.y;T3[10]=c.z;T3[11]=c.w; }
            p = im + (size_t)(y0 + 1) * IMG_W + (x0 - 4);
            { float4 a=*(const float4*)p, b=*(const float4*)(p+4), c=*(const float4*)(p+8);
              T4[0]=a.x;T4[1]=a.y;T4[2]=a.z;T4[3]=a.w;T4[4]=b.x;T4[5]=b.y;T4[6]=b.z;T4[7]=b.w;
              T4[8]=c.x;T4[9]=c.y;T4[10]=c.z;T4[11]=c.w; }
            p = im + (size_t)(y0 + 2) * IMG_W + (x0 - 4);
            { float4 a=*(const float4*)p, b=*(const float4*)(p+4), c=*(const float4*)(p+8);
              T5[0]=a.x;T5[1]=a.y;T5[2]=a.z;T5[3]=a.w;T5[4]=b.x;T5[5]=b.y;T5[6]=b.z;T5[7]=b.w;
              T5[8]=c.x;T5[9]=c.y;T5[10]=c.z;T5[11]=c.w; }
            p = im + (size_t)(y0 + 3) * IMG_W + x0;
            { float2 v = *(const float2*)(p - 2); T6[0]=v.x; T6[1]=v.y; }
            { float4 v = *(const float4*)p;       T6[2]=v.x; T6[3]=v.y; T6[4]=v.z; T6[5]=v.w; }
            { float2 v = *(const float2*)(p + 4); T6[6]=v.x; T6[7]=v.y; }
            p = im + (size_t)(y0 + 4) * IMG_W + x0;
            T7[0] = p[-1];
            { float4 v = *(const float4*)p; T7[1]=v.x; T7[2]=v.y; T7[3]=v.z; T7[4]=v.w; }
            T7[5] = p[4];
        }

        float4 res0, res1;
        float* r0p = (float*)&res0;
        float* r1p = (float*)&res1;
#pragma unroll
        for (int p = 0; p < 4; p++) {
            float d[16];
            // ---- center row y0 (roles: R0..R6 = T0..T6) ----
            {
                float ctr = T3[p + 4];
                d[0]  = T3[p + 1] - ctr;   // (0,-3)
                d[1]  = T4[p + 1] - ctr;   // (1,-3)
                d[2]  = T5[p + 2] - ctr;   // (2,-2)  T5 base x0-4
                d[3]  = T6[p + 1] - ctr;   // (3,-1)  T6 base x0-2
                d[4]  = T6[p + 2] - ctr;   // (3, 0)
                d[5]  = T6[p + 3] - ctr;   // (3, 1)
                d[6]  = T5[p + 6] - ctr;   // (2, 2)
                d[7]  = T4[p + 7] - ctr;   // (1, 3)
                d[8]  = T3[p + 7] - ctr;   // (0, 3)
                d[9]  = T2[p + 7] - ctr;   // (-1,3)
                d[10] = T1[p + 4] - ctr;   // (-2,2)
                d[11] = T0[p + 2] - ctr;   // (-3,1)
                d[12] = T0[p + 1] - ctr;   // (-3,0)
                d[13] = T0[p + 0] - ctr;   // (-3,-1)
                d[14] = T1[p + 0] - ctr;   // (-2,-2)
                d[15] = T2[p + 1] - ctr;   // (-1,-3)
                r0p[p] = detect16(d);
            }
            // ---- center row y0+1 (roles: R0..R6 = T1..T7) ----
            {
                float ctr = T4[p + 4];
                d[0]  = T4[p + 1] - ctr;   // (0,-3)
                d[1]  = T5[p + 1] - ctr;   // (1,-3)  T5 base x0-4
                d[2]  = T6[p + 0] - ctr;   // (2,-2)  T6 base x0-2
                d[3]  = T7[p + 0] - ctr;   // (3,-1)  T7 base x0-1
                d[4]  = T7[p + 1] - ctr;   // (3, 0)
                d[5]  = T7[p + 2] - ctr;   // (3, 1)
                d[6]  = T6[p + 4] - ctr;   // (2, 2)
                d[7]  = T5[p + 7] - ctr;   // (1, 3)
                d[8]  = T4[p + 7] - ctr;   // (0, 3)
                d[9]  = T3[p + 7] - ctr;   // (-1,3)
                d[10] = T2[p + 6] - ctr;   // (-2,2)  T2 base x0-4
                d[11] = T1[p + 3] - ctr;   // (-3,1)  T1 base x0-2
                d[12] = T1[p + 2] - ctr;   // (-3,0)
                d[13] = T1[p + 1] - ctr;   // (-3,-1)
                d[14] = T2[p + 2] - ctr;   // (-2,-2)
                d[15] = T3[p + 1] - ctr;   // (-1,-3)
                r1p[p] = detect16(d);
            }
        }
        *(float4*)op0 = res0;
        *(float4*)op1 = res1;
    } else {
        // Border path: scalar loads with replicate-clamp (rare).
#pragma unroll
        for (int rr = 0; rr < 2; rr++) {
            int y = y0 + rr;
            float* op = (rr == 0) ? op0 : op1;
#pragma unroll
            for (int p = 0; p < 4; p++) {
                int x = x0 + p;
                float center = __ldg(im + (size_t)y * IMG_W + x);
                unsigned dark = 0u, bright = 0u;
#pragma unroll
                for (int i = 0; i < 16; i++) {
                    int yy = min(max(y + DY[i], 0), IMG_H - 1);
                    int xx = min(max(x + DX[i], 0), IMG_W - 1);
                    float diff = __ldg(im + (size_t)yy * IMG_W + xx) - center;
                    if (diff >=  THR) dark   |= (1u << i);
                    if (diff <= -THR) bright |= (1u << i);
                }
                unsigned det = run9w(dark) | run9w(bright);
                op[p] = __uint_as_float(min(det, 1u) * 0x3F800000u);
            }
        }
    }
}

extern "C" void kernel_launch(void* const* d_in, const int* in_sizes, int n_in,
                              void* d_out, int out_size)
{
    const float* img = (const float*)d_in[0];
    float* out = (float*)d_out;
    int N = in_sizes[0] / (IMG_H * IMG_W);

    dim3 block(96, 1, 1);
    // x: 1920/4 px-per-thread = 480 threads -> 5 blocks of 96
    // y: two rows per thread -> 540
    dim3 grid(IMG_W / 4 / 96, IMG_H / 2, N);
    fast_score_kernel<<<grid, block>>>(img, out, N);
}